// round 10
// baseline (speedup 1.0000x reference)
#include <cuda_runtime.h>
#include <cuda_bf16.h>
#include <cstdint>
#include <cstddef>

// PoolingRetriever collapses: seqlen==1 -> softmax of one logit == 1
// -> out = (x@Wv.T + bv) @ Wo.T + bo.   Wq/bq/Wk/bk/q_state dead.
// R7: R6 (mma.sync bf16 3-pass hi/lo) + latency pipelining:
//   - stage-1: double-buffered x chunks, register-staged LDG prefetch, 1 sync/chunk
//   - stage-2: ping-pong prefetch of Wo b-fragments

#define DIMX 768
#define NH   64
#define TM   128
#define NTHR 256
#define KC   64                 // x K-chunk (bf16 row = 128 B = SW128 atom)
#define NCHUNK (DIMX / KC)      // 12

// smem (dynamic, bytes): buf b at b*32768 (hi), +16384 (lo); tmp at 65536
#define OFF_TH 65536
#define OFF_TL 81920
#define SMEM_TOTAL 98304

// B fragments prepped in gmem, per-lane mma layout.
__device__ __align__(16) uint2 g_wv_fh[48 * 8 * 32];
__device__ __align__(16) uint2 g_wv_fl[48 * 8 * 32];
__device__ __align__(16) uint2 g_wo_fh[96 * 4 * 32];
__device__ __align__(16) uint2 g_wo_fl[96 * 4 * 32];

static __device__ __forceinline__ uint32_t smem_u32(const void* p) {
    uint32_t a;
    asm("{ .reg .u64 t; cvta.to.shared.u64 t, %1; cvt.u32.u64 %0, t; }"
        : "=r"(a) : "l"(p));
    return a;
}
static __device__ __forceinline__ uint32_t swz(uint32_t b) {
    return b ^ ((b >> 3) & 0x70);
}
static __device__ __forceinline__ void split1(float v, __nv_bfloat16& h,
                                              __nv_bfloat16& l) {
    h = __float2bfloat16(v);
    l = __float2bfloat16(v - __bfloat162float(h));
}
static __device__ __forceinline__ uint32_t packbf(__nv_bfloat16 lo,
                                                  __nv_bfloat16 hi) {
    __nv_bfloat162 t; t.x = lo; t.y = hi;
    return *(uint32_t*)&t;
}

#define LDMX4(r0, r1, r2, r3, addr)                                          \
    asm volatile("ldmatrix.sync.aligned.m8n8.x4.shared.b16 {%0,%1,%2,%3}, [%4];" \
                 : "=r"(r0), "=r"(r1), "=r"(r2), "=r"(r3) : "r"(addr))

static __device__ __forceinline__ void mma16816(float* c, const uint32_t* a,
                                                uint2 b) {
    asm volatile(
        "mma.sync.aligned.m16n8k16.row.col.f32.bf16.bf16.f32 "
        "{%0,%1,%2,%3}, {%4,%5,%6,%7}, {%8,%9}, {%0,%1,%2,%3};"
        : "+f"(c[0]), "+f"(c[1]), "+f"(c[2]), "+f"(c[3])
        : "r"(a[0]), "r"(a[1]), "r"(a[2]), "r"(a[3]), "r"(b.x), "r"(b.y));
}

// ---------------- prep: split weights into per-lane B fragments -------------
__global__ void prep_kernel(const float* __restrict__ Wv,
                            const float* __restrict__ Wo) {
    int idx = blockIdx.x * blockDim.x + threadIdx.x;
    if (idx < 48 * 8 * 32) {
        int lane = idx & 31, nt = (idx >> 5) & 7, ktg = idx >> 8;
        int n = nt * 8 + (lane >> 2);
        int k = ktg * 16 + (lane & 3) * 2;
        float w0 = Wv[n * DIMX + k],     w1 = Wv[n * DIMX + k + 1];
        float w2 = Wv[n * DIMX + k + 8], w3 = Wv[n * DIMX + k + 9];
        __nv_bfloat16 h0, l0, h1, l1, h2, l2, h3, l3;
        split1(w0, h0, l0); split1(w1, h1, l1);
        split1(w2, h2, l2); split1(w3, h3, l3);
        g_wv_fh[idx] = make_uint2(packbf(h0, h1), packbf(h2, h3));
        g_wv_fl[idx] = make_uint2(packbf(l0, l1), packbf(l2, l3));
    } else if (idx < 2 * 12288) {
        int t = idx - 12288;
        int lane = t & 31, kt = (t >> 5) & 3, nt = t >> 7;
        int n = nt * 8 + (lane >> 2);        // out column 0..767
        int k = kt * 16 + (lane & 3) * 2;    // 0..63
        float w0 = Wo[n * NH + k],     w1 = Wo[n * NH + k + 1];
        float w2 = Wo[n * NH + k + 8], w3 = Wo[n * NH + k + 9];
        __nv_bfloat16 h0, l0, h1, l1, h2, l2, h3, l3;
        split1(w0, h0, l0); split1(w1, h1, l1);
        split1(w2, h2, l2); split1(w3, h3, l3);
        g_wo_fh[t] = make_uint2(packbf(h0, h1), packbf(h2, h3));
        g_wo_fl[t] = make_uint2(packbf(l0, l1), packbf(l2, l3));
    }
}

// ---------------- fused HMMA kernel -----------------------------------------
__global__ __launch_bounds__(NTHR, 2) void fused_kernel(
        const float* __restrict__ x, const float* __restrict__ bv,
        const float* __restrict__ bo, float* __restrict__ out, int B) {
    extern __shared__ __align__(128) char smem[];
    const uint32_t sb = smem_u32(smem);
    const int tid = threadIdx.x;
    const int wid = tid >> 5, lane = tid & 31;
    const int wm = wid >> 1, wn = wid & 1;   // warps: 4 (M) x 2 (N)
    const int brow = blockIdx.x * TM;
    const int lrow = lane >> 2, lk2 = (lane & 3) * 2;

    // per-thread x-load geometry (constant across chunks)
    const int xr = tid >> 4;           // rows: tid/16 + s*16
    const int xk4 = tid & 15;

    float4 xp[8];                      // register-staged x prefetch

    auto LOADX = [&](int ch) {
        #pragma unroll
        for (int s = 0; s < 8; s++) {
            int gr = brow + xr + s * 16; if (gr >= B) gr = B - 1;
            xp[s] = *(const float4*)&x[(size_t)gr * DIMX + ch * KC + xk4 * 4];
        }
    };
    auto STOREX = [&](int b) {
        char* bh = smem + b * 32768;
        char* bl = bh + 16384;
        #pragma unroll
        for (int s = 0; s < 8; s++) {
            int r = xr + s * 16;
            __nv_bfloat16 h0, l0, h1, l1, h2, l2, h3, l3;
            split1(xp[s].x, h0, l0); split1(xp[s].y, h1, l1);
            split1(xp[s].z, h2, l2); split1(xp[s].w, h3, l3);
            uint32_t so = swz((uint32_t)(r * 128 + xk4 * 8));
            *(uint2*)(bh + so) = make_uint2(packbf(h0, h1), packbf(h2, h3));
            *(uint2*)(bl + so) = make_uint2(packbf(l0, l1), packbf(l2, l3));
        }
    };

    // ----- Stage 1: tmp[128x64] = x @ Wv.T (3-pass), accum in regs -----
    float c1[2][4][4];
    #pragma unroll
    for (int mt = 0; mt < 2; mt++)
        #pragma unroll
        for (int nt = 0; nt < 4; nt++)
            #pragma unroll
            for (int q = 0; q < 4; q++) c1[mt][nt][q] = 0.0f;

    LOADX(0);
    STOREX(0);
    __syncthreads();

    for (int ch = 0; ch < NCHUNK; ch++) {
        const uint32_t bufH = sb + (uint32_t)(ch & 1) * 32768;
        const uint32_t bufL = bufH + 16384;
        if (ch + 1 < NCHUNK) LOADX(ch + 1);   // LDG in flight during mmas

        #pragma unroll
        for (int kt = 0; kt < 4; kt++) {
            int ktg = ch * 4 + kt;
            uint32_t ah[2][4], al[2][4];
            #pragma unroll
            for (int mt = 0; mt < 2; mt++) {
                uint32_t lb = (uint32_t)((wm * 32 + mt * 16 + (lane & 15)) * 128 +
                                         kt * 32 + (lane >> 4) * 16);
                uint32_t so = swz(lb);
                LDMX4(ah[mt][0], ah[mt][1], ah[mt][2], ah[mt][3], bufH + so);
                LDMX4(al[mt][0], al[mt][1], al[mt][2], al[mt][3], bufL + so);
            }
            #pragma unroll
            for (int nt = 0; nt < 4; nt++) {
                int ntg = wn * 4 + nt;
                uint2 bh = g_wv_fh[(ktg * 8 + ntg) * 32 + lane];
                uint2 bl = g_wv_fl[(ktg * 8 + ntg) * 32 + lane];
                #pragma unroll
                for (int mt = 0; mt < 2; mt++) {
                    mma16816(c1[mt][nt], ah[mt], bh);
                    mma16816(c1[mt][nt], ah[mt], bl);
                    mma16816(c1[mt][nt], al[mt], bh);
                }
            }
        }
        if (ch + 1 < NCHUNK) {
            STOREX((ch + 1) & 1);
            __syncthreads();
        }
    }
    __syncthreads();   // all reads of last buffer done before tmp write reuse

    // ----- stage-1 epilogue: +bv, split, store tmp hi/lo swizzled -----
    #pragma unroll
    for (int mt = 0; mt < 2; mt++) {
        #pragma unroll
        for (int nt = 0; nt < 4; nt++) {
            int c = wn * 32 + nt * 8 + lk2;
            float b0 = __ldg(&bv[c]), b1 = __ldg(&bv[c + 1]);
            int r0 = wm * 32 + mt * 16 + lrow;
            float v0 = c1[mt][nt][0] + b0, v1 = c1[mt][nt][1] + b1;
            float v2 = c1[mt][nt][2] + b0, v3 = c1[mt][nt][3] + b1;
            __nv_bfloat16 h0, l0, h1, l1, h2, l2, h3, l3;
            split1(v0, h0, l0); split1(v1, h1, l1);
            split1(v2, h2, l2); split1(v3, h3, l3);
            uint32_t s0 = swz((uint32_t)(r0 * 128 + c * 2));
            uint32_t s1 = swz((uint32_t)((r0 + 8) * 128 + c * 2));
            *(uint32_t*)(smem + OFF_TH + s0) = packbf(h0, h1);
            *(uint32_t*)(smem + OFF_TL + s0) = packbf(l0, l1);
            *(uint32_t*)(smem + OFF_TH + s1) = packbf(h2, h3);
            *(uint32_t*)(smem + OFF_TL + s1) = packbf(l2, l3);
        }
    }
    __syncthreads();

    // ----- Stage 2: out[128x768] = tmp @ Wo.T + bo -----
    uint32_t a2h[2][4][4], a2l[2][4][4];
    #pragma unroll
    for (int mt = 0; mt < 2; mt++) {
        #pragma unroll
        for (int kt = 0; kt < 4; kt++) {
            uint32_t lb = (uint32_t)((wm * 32 + mt * 16 + (lane & 15)) * 128 +
                                     kt * 32 + (lane >> 4) * 16);
            uint32_t so = swz(lb);
            LDMX4(a2h[mt][kt][0], a2h[mt][kt][1], a2h[mt][kt][2],
                  a2h[mt][kt][3], sb + OFF_TH + so);
            LDMX4(a2l[mt][kt][0], a2l[mt][kt][1], a2l[mt][kt][2],
                  a2l[mt][kt][3], sb + OFF_TL + so);
        }
    }

    // ping-pong prefetched Wo fragments
    uint2 pbh[2][4], pbl[2][4];
    {
        int ntg0 = wn * 48;
        #pragma unroll
        for (int kt = 0; kt < 4; kt++) {
            pbh[0][kt] = g_wo_fh[(ntg0 * 4 + kt) * 32 + lane];
            pbl[0][kt] = g_wo_fl[(ntg0 * 4 + kt) * 32 + lane];
        }
    }

    #pragma unroll 2
    for (int ct = 0; ct < 48; ct++) {
        const int cur = ct & 1, nxt = cur ^ 1;
        const int ntg = wn * 48 + ct;
        if (ct < 47) {
            #pragma unroll
            for (int kt = 0; kt < 4; kt++) {
                pbh[nxt][kt] = g_wo_fh[((ntg + 1) * 4 + kt) * 32 + lane];
                pbl[nxt][kt] = g_wo_fl[((ntg + 1) * 4 + kt) * 32 + lane];
            }
        }
        float cc[2][4];
        #pragma unroll
        for (int mt = 0; mt < 2; mt++)
            #pragma unroll
            for (int q = 0; q < 4; q++) cc[mt][q] = 0.0f;
        #pragma unroll
        for (int kt = 0; kt < 4; kt++) {
            #pragma unroll
            for (int mt = 0; mt < 2; mt++) {
                mma16816(cc[mt], a2h[mt][kt], pbh[cur][kt]);
                mma16816(cc[mt], a2h[mt][kt], pbl[cur][kt]);
                mma16816(cc[mt], a2l[mt][kt], pbh[cur][kt]);
            }
        }
        int c = ntg * 8 + lk2;
        float2 bb = *(const float2*)&bo[c];
        #pragma unroll
        for (int mt = 0; mt < 2; mt++) {
            int gr = brow + wm * 32 + mt * 16 + lrow;
            if (gr < B) {
                float2 o0 = make_float2(cc[mt][0] + bb.x, cc[mt][1] + bb.y);
                float2 o1 = make_float2(cc[mt][2] + bb.x, cc[mt][3] + bb.y);
                *(float2*)&out[(size_t)gr * DIMX + c] = o0;
                if (gr + 8 < B)
                    *(float2*)&out[(size_t)(gr + 8) * DIMX + c] = o1;
            }
        }
    }
}

extern "C" void kernel_launch(void* const* d_in, const int* in_sizes, int n_in,
                              void* d_out, int out_size) {
    // metadata order: x, q_state, Wq, bq, Wk, bk, Wv, bv, Wo, bo
    const float* x  = (const float*)d_in[0];
    const float* Wv = (const float*)d_in[6];
    const float* bv = (const float*)d_in[7];
    const float* Wo = (const float*)d_in[8];
    const float* bo = (const float*)d_in[9];
    float* out = (float*)d_out;

    const int B = in_sizes[0] / DIMX;

    cudaFuncSetAttribute(fused_kernel,
                         cudaFuncAttributeMaxDynamicSharedMemorySize,
                         SMEM_TOTAL);

    prep_kernel<<<(2 * 12288 + 255) / 256, 256>>>(Wv, Wo);
    const int grid = (B + TM - 1) / TM;
    fused_kernel<<<grid, NTHR, SMEM_TOTAL>>>(x, bv, bo, out, B);
}